// round 12
// baseline (speedup 1.0000x reference)
#include <cuda_runtime.h>
#include <cuda_bf16.h>
#include <cstdint>

#define T_SEQ   4096
#define D_MODEL 1024
#define NH      16
#define NKV     4
#define HD      64
#define QL      512
#define KVL     256
#define NTP     2080                    // qtile*(qtile+1)/2 + kt pairs
#define TRI_ENT 8519680                 // NTP * 4096 entries per head

// ---------------- scratch (device globals; all f32, values bf16-rounded) -----
static __device__ float g_qlat_raw[T_SEQ * QL];
static __device__ float g_qlat    [T_SEQ * QL];
static __device__ float g_q       [T_SEQ * NH * HD];
static __device__ float g_q_ro    [T_SEQ * NH * HD];
static __device__ float g_kvraw   [T_SEQ * KVL];
static __device__ float g_kvlat   [T_SEQ * KVL];
static __device__ float g_k       [T_SEQ * NKV * HD];
static __device__ float g_k_ro    [T_SEQ * NKV * HD];
static __device__ float g_v       [T_SEQ * NKV * HD];
static __device__ float g_attn    [T_SEQ * D_MODEL];
static __device__ float g_m       [NH * T_SEQ];
static __device__ float g_l       [NH * T_SEQ];

// causal-packed scratch: scores bf16(q.k), later overwritten with probs
static __device__ __nv_bfloat16 g_scores[(size_t)NH * TRI_ENT];

// ---------------- helpers -----------------------------------------------------
__device__ __forceinline__ float bf16r(float x) {
    return __bfloat162float(__float2bfloat16(x));
}

typedef unsigned long long u64;

__device__ __forceinline__ u64 pack2(float lo, float hi) {
    u64 r;
    asm("mov.b64 %0, {%1, %2};" : "=l"(r) : "f"(lo), "f"(hi));
    return r;
}
__device__ __forceinline__ void unpack2(u64 v, float& lo, float& hi) {
    asm("mov.b64 {%0, %1}, %2;" : "=f"(lo), "=f"(hi) : "l"(v));
}
__device__ __forceinline__ u64 d2u(double d) {
    return (u64)__double_as_longlong(d);
}
__device__ __forceinline__ u64 fma2(u64 a, u64 b, u64 c) {
    u64 d;
    asm("fma.rn.f32x2 %0, %1, %2, %3;" : "=l"(d) : "l"(a), "l"(b), "l"(c));
    return d;
}

// Deterministic ~1-ulp exp, fmaf-only (identical since round 7).
__device__ __forceinline__ float exp_acc(float x) {
    x = fmaxf(x, -87.0f);
    float n = rintf(x * 1.44269504088896340736f);
    float r = fmaf(n, -0.693145751953125f, x);
    r = fmaf(n, -1.42860677e-06f, r);
    float p = 1.9841269841e-04f;
    p = fmaf(p, r, 1.3888888889e-03f);
    p = fmaf(p, r, 8.3333333333e-03f);
    p = fmaf(p, r, 4.1666666667e-02f);
    p = fmaf(p, r, 1.6666666667e-01f);
    p = fmaf(p, r, 0.5f);
    p = fmaf(p, r, 1.0f);
    p = fmaf(p, r, 1.0f);
    int in = (int)n;
    return p * __int_as_float((in + 127) << 23);
}

// ---------------- GEMM: 64x64 tile, BK=32, 128 threads, FFMA2 core -----------
__global__ void __launch_bounds__(128, 5)
gemm_ffma2(const float* __restrict__ A,
           const float* __restrict__ B,
           float* __restrict__ C,
           int M, int N, int K) {
    __shared__ float As[32][68];
    __shared__ float Bs[32][68];

    const int tid = threadIdx.x;
    const int tx = tid & 15;
    const int ty = tid >> 4;
    const int row0 = blockIdx.y * 64;
    const int col0 = blockIdx.x * 64;

    const int a_row  = tid & 63;
    const int a_half = tid >> 6;
    const int b_row  = tid >> 2;
    const int b_col  = (tid & 3) * 16;

    u64 acc2[4][4];
#pragma unroll
    for (int p = 0; p < 4; p++)
#pragma unroll
        for (int j = 0; j < 4; j++) acc2[p][j] = 0ull;

    for (int k0 = 0; k0 < K; k0 += 32) {
        {
            const float* ap = A + (size_t)(row0 + a_row) * K + k0 + a_half * 16;
            float av[16];
#pragma unroll
            for (int u = 0; u < 4; u++)
                *(float4*)&av[u * 4] = ((const float4*)ap)[u];
#pragma unroll
            for (int u = 0; u < 16; u++)
                As[a_half * 16 + u][a_row] = av[u];
        }
        {
            const float* bp = B + (size_t)(k0 + b_row) * N + col0 + b_col;
#pragma unroll
            for (int u = 0; u < 4; u++)
                *(float4*)&Bs[b_row][b_col + u * 4] = ((const float4*)bp)[u];
        }
        __syncthreads();

#pragma unroll 4
        for (int kk = 0; kk < 32; kk++) {
            float4 bf = *(const float4*)&Bs[kk][tx * 4];
            u64 b0 = pack2(bf.x, bf.x);
            u64 b1 = pack2(bf.y, bf.y);
            u64 b2 = pack2(bf.z, bf.z);
            u64 b3 = pack2(bf.w, bf.w);
            double2 a01 = *(const double2*)&As[kk][ty * 8];
            double2 a23 = *(const double2*)&As[kk][ty * 8 + 4];
            u64 ap_[4] = { d2u(a01.x), d2u(a01.y), d2u(a23.x), d2u(a23.y) };
#pragma unroll
            for (int p = 0; p < 4; p++) {
                acc2[p][0] = fma2(ap_[p], b0, acc2[p][0]);
                acc2[p][1] = fma2(ap_[p], b1, acc2[p][1]);
                acc2[p][2] = fma2(ap_[p], b2, acc2[p][2]);
                acc2[p][3] = fma2(ap_[p], b3, acc2[p][3]);
            }
        }
        __syncthreads();
    }

#pragma unroll
    for (int p = 0; p < 4; p++) {
        float lo0, hi0, lo1, hi1, lo2, hi2, lo3, hi3;
        unpack2(acc2[p][0], lo0, hi0);
        unpack2(acc2[p][1], lo1, hi1);
        unpack2(acc2[p][2], lo2, hi2);
        unpack2(acc2[p][3], lo3, hi3);
        float4 ve = make_float4(bf16r(lo0), bf16r(lo1), bf16r(lo2), bf16r(lo3));
        float4 vo = make_float4(bf16r(hi0), bf16r(hi1), bf16r(hi2), bf16r(hi3));
        *(float4*)&C[(size_t)(row0 + ty * 8 + 2 * p)     * N + col0 + tx * 4] = ve;
        *(float4*)&C[(size_t)(row0 + ty * 8 + 2 * p + 1) * N + col0 + tx * 4] = vo;
    }
}

// ---------------- RMSNorm (same FP ops) ---------------------------------------
__global__ void rmsnorm_kernel(const float* __restrict__ in,
                               const float* __restrict__ scale,
                               float* __restrict__ out,
                               int cols) {
    const int row = blockIdx.x;
    const int tid = threadIdx.x;
    const float* x = in + (size_t)row * cols;
    float* y = out + (size_t)row * cols;

    __shared__ float red[256];
    float s = 0.0f;
    for (int c = tid; c < cols; c += 256) {
        float v = x[c];
        s = fmaf(v, v, s);
    }
    red[tid] = s;
    __syncthreads();
    for (int off = 128; off > 0; off >>= 1) {
        if (tid < off) red[tid] += red[tid + off];
        __syncthreads();
    }
    float rms = __fsqrt_rn(red[0] / (float)cols + 1e-6f);
    for (int c = tid; c < cols; c += 256)
        y[c] = bf16r(__fdiv_rn(x[c], rms) * scale[c]);
}

// ---------------- RoPE (same FP ops) -------------------------------------------
__global__ void rope_kernel(const float* __restrict__ in,
                            const float* __restrict__ sin_t,
                            const float* __restrict__ cos_t,
                            float* __restrict__ out,
                            int heads) {
    int idx = blockIdx.x * blockDim.x + threadIdx.x;
    int total = T_SEQ * heads * HD;
    if (idx >= total) return;
    int d = idx & 63;
    int t = (idx >> 6) / heads;
    float xv = in[idx];
    float rot = (d < 32) ? -in[idx + 32] : in[idx - 32];
    float r1 = bf16r(xv * cos_t[t * HD + d]);
    float r2 = bf16r(rot * sin_t[t * HD + d]);
    out[idx] = bf16r(r1 + r2);
}

// ---------------- attention kernel A: QK + scores + m + l ---------------------
__global__ void __launch_bounds__(128, 5)
attn_qk_kernel(const float* __restrict__ Q,
               const float* __restrict__ Kc,
               float* __restrict__ Mg,
               float* __restrict__ Lg,
               __nv_bfloat16* __restrict__ Sc) {
    __shared__ float QP[64][68];   // Qs[i][row]
    __shared__ float KV[64][68];   // Ks[i][key]
    __shared__ float m_s[64];

    const int qtile = (int)gridDim.x - 1 - (int)blockIdx.x;
    const int h = blockIdx.y;
    const int hk = h >> 2;
    const int tid = threadIdx.x;
    const size_t sbase = (size_t)h * TRI_ENT +
                         (size_t)qtile * (qtile + 1) / 2 * 4096;

    const int rg = tid >> 3;    // 0..15 -> 4 rows each
    const int kg = tid & 7;     // 0..7  -> 8 keys each

    {
        const int r_ld = tid >> 1, dh = tid & 1;
        const float* qp = Q + (size_t)(qtile * 64 + r_ld) * D_MODEL + h * HD + dh * 32;
        float qv[32];
#pragma unroll
        for (int u = 0; u < 8; u++)
            *(float4*)&qv[u * 4] = ((const float4*)qp)[u];
#pragma unroll
        for (int u = 0; u < 32; u++)
            QP[dh * 32 + u][r_ld] = qv[u];
    }

    float mreg[4] = { -1e30f, -1e30f, -1e30f, -1e30f };

    for (int kt = 0; kt <= qtile; kt++) {
        __syncthreads();
        {
            const int key = tid >> 1, dh = tid & 1;
            const float* kp = Kc + (size_t)(kt * 64 + key) * (NKV * HD) + hk * HD + dh * 32;
            float kv[32];
#pragma unroll
            for (int u = 0; u < 8; u++)
                *(float4*)&kv[u * 4] = ((const float4*)kp)[u];
#pragma unroll
            for (int u = 0; u < 32; u++)
                KV[dh * 32 + u][key] = kv[u];
        }
        __syncthreads();

        u64 alo[4][4], ahi[4][4];
#pragma unroll
        for (int a = 0; a < 4; a++)
#pragma unroll
            for (int b = 0; b < 4; b++) { alo[a][b] = 0ull; ahi[a][b] = 0ull; }

#pragma unroll 8
        for (int i = 0; i < 32; i++) {
            float4 qv = *(const float4*)&QP[i][rg * 4];
            double2 ka = *(const double2*)&KV[i][kg * 8];
            double2 kb = *(const double2*)&KV[i][kg * 8 + 4];
            u64 kp_[4] = { d2u(ka.x), d2u(ka.y), d2u(kb.x), d2u(kb.y) };
            u64 q_[4] = { pack2(qv.x, qv.x), pack2(qv.y, qv.y),
                          pack2(qv.z, qv.z), pack2(qv.w, qv.w) };
#pragma unroll
            for (int a = 0; a < 4; a++)
#pragma unroll
                for (int b = 0; b < 4; b++)
                    alo[a][b] = fma2(q_[a], kp_[b], alo[a][b]);
        }
#pragma unroll 8
        for (int i = 32; i < 64; i++) {
            float4 qv = *(const float4*)&QP[i][rg * 4];
            double2 ka = *(const double2*)&KV[i][kg * 8];
            double2 kb = *(const double2*)&KV[i][kg * 8 + 4];
            u64 kp_[4] = { d2u(ka.x), d2u(ka.y), d2u(kb.x), d2u(kb.y) };
            u64 q_[4] = { pack2(qv.x, qv.x), pack2(qv.y, qv.y),
                          pack2(qv.z, qv.z), pack2(qv.w, qv.w) };
#pragma unroll
            for (int a = 0; a < 4; a++)
#pragma unroll
                for (int b = 0; b < 4; b++)
                    ahi[a][b] = fma2(q_[a], kp_[b], ahi[a][b]);
        }

        float scv[8][4];
#pragma unroll
        for (int b = 0; b < 4; b++)
#pragma unroll
            for (int a = 0; a < 4; a++) {
                float l0, l1, h0, h1;
                unpack2(alo[a][b], l0, l1);
                unpack2(ahi[a][b], h0, h1);
                scv[b * 2][a]     = l0 + h0;
                scv[b * 2 + 1][a] = l1 + h1;
            }
#pragma unroll
        for (int jj = 0; jj < 8; jj++) {
            int j = kg * 8 + jj;
            int gj = kt * 64 + j;
            __nv_bfloat162 pa = __floats2bfloat162_rn(scv[jj][0], scv[jj][1]);
            __nv_bfloat162 pb = __floats2bfloat162_rn(scv[jj][2], scv[jj][3]);
            uint2 st;
            st.x = *(unsigned int*)&pa;
            st.y = *(unsigned int*)&pb;
            *(uint2*)(Sc + sbase + (size_t)gj * 64 + rg * 4) = st;
#pragma unroll
            for (int a = 0; a < 4; a++) {
                float s = bf16r(scv[jj][a]) * 0.125f;
                int trow = qtile * 64 + rg * 4 + a;
                if (gj <= trow) mreg[a] = fmaxf(mreg[a], s);
            }
        }
    }

#pragma unroll
    for (int a = 0; a < 4; a++) {
        float v = mreg[a];
        v = fmaxf(v, __shfl_xor_sync(0xffffffffu, v, 1));
        v = fmaxf(v, __shfl_xor_sync(0xffffffffu, v, 2));
        v = fmaxf(v, __shfl_xor_sync(0xffffffffu, v, 4));
        mreg[a] = v;
    }
    if (kg == 0) {
#pragma unroll
        for (int a = 0; a < 4; a++) {
            m_s[rg * 4 + a] = mreg[a];
            Mg[h * T_SEQ + qtile * 64 + rg * 4 + a] = mreg[a];
        }
    }
    __syncthreads();

    // ---- pass 2: l chain (byte-identical structure to R10/R11) ----
    {
        const int r2 = tid >> 1, hf2 = tid & 1;
        const unsigned pair_mask = 0x3u << ((tid & 31) & ~1);
        const float m = m_s[r2];
        float l = 0.0f;
        for (int kt = 0; kt <= qtile; kt++) {
            const int jmax = (kt == qtile) ? r2 : 63;
            int j = 0;
            for (; j + 1 <= jmax; j += 2) {
                int jm = j + hf2;
                float s = __bfloat162float(Sc[sbase + (size_t)(kt * 64 + jm) * 64 + r2]) * 0.125f;
                float e = exp_acc(s - m);
                float eo = __shfl_xor_sync(pair_mask, e, 1);
                float e_even = hf2 ? eo : e;
                float e_odd  = hf2 ? e  : eo;
                l += e_even;
                l += e_odd;
            }
            if (j <= jmax) {
                float s = __bfloat162float(Sc[sbase + (size_t)(kt * 64 + j) * 64 + r2]) * 0.125f;
                l += exp_acc(s - m);
            }
        }
        if (hf2 == 0) Lg[h * T_SEQ + qtile * 64 + r2] = l;
    }
}

// ---------------- prob kernel: scratch scores -> probs (in place) -------------
// p = bf16( exp_acc(s*0.125 - m) / l ), masked -> 0. Element-local, any order.
__global__ void __launch_bounds__(256)
prob_kernel(__nv_bfloat16* __restrict__ Sc,
            const float* __restrict__ Mg,
            const float* __restrict__ Lg) {
    const int tp = blockIdx.x;          // tile-pair index 0..NTP-1
    const int h = blockIdx.y;
    // invert tp -> qtile (exact with integer correction)
    int qt = (int)((__fsqrt_rn(8.0f * (float)tp + 1.0f) - 1.0f) * 0.5f);
    while ((qt + 1) * (qt + 2) / 2 <= tp) qt++;
    while (qt * (qt + 1) / 2 > tp) qt--;
    const int kt = tp - qt * (qt + 1) / 2;

    __nv_bfloat16* base = Sc + (size_t)h * TRI_ENT + (size_t)tp * 4096;
    const int tid = threadIdx.x;
    const int j = tid >> 2;             // 0..63
    const int r0 = (tid & 3) * 16;      // 16 consecutive rows
    const int gj = kt * 64 + j;

    __nv_bfloat16* ptr = base + j * 64 + r0;
    // 16 bf16 = 2 uint4
    uint4 w0 = ((const uint4*)ptr)[0];
    uint4 w1 = ((const uint4*)ptr)[1];
    unsigned int ws[8] = { w0.x, w0.y, w0.z, w0.w, w1.x, w1.y, w1.z, w1.w };
    unsigned int outw[8];
    const float* mrow = Mg + h * T_SEQ + qt * 64 + r0;
    const float* lrow = Lg + h * T_SEQ + qt * 64 + r0;

#pragma unroll
    for (int wi = 0; wi < 8; wi++) {
        unsigned int word = ws[wi];
        unsigned int res = 0;
#pragma unroll
        for (int e = 0; e < 2; e++) {
            int rr = wi * 2 + e;
            int row = qt * 64 + r0 + rr;
            float p = 0.0f;
            if (gj <= row) {
                float sv = __uint_as_float(e ? (word & 0xffff0000u) : (word << 16));
                float s = sv * 0.125f;
                p = bf16r(__fdiv_rn(exp_acc(s - mrow[rr]), lrow[rr]));
            }
            __nv_bfloat16 pb = __float2bfloat16(p);
            unsigned short pv = *(unsigned short*)&pb;
            res |= (unsigned int)pv << (e * 16);
        }
        outw[wi] = res;
    }
    ((uint4*)ptr)[0] = make_uint4(outw[0], outw[1], outw[2], outw[3]);
    ((uint4*)ptr)[1] = make_uint4(outw[4], outw[5], outw[6], outw[7]);
}

// ---------------- attention kernel B: PV GEMM over precomputed probs ----------
__global__ void __launch_bounds__(128, 6)
attn_pv_kernel(const float* __restrict__ Vc,
               float* __restrict__ O,
               const __nv_bfloat16* __restrict__ Sc) {
    __shared__ float Ps[64][68];   // probs [row][j]
    __shared__ float Vs[64][68];   // V [j][dim]

    const int qtile = (int)gridDim.x - 1 - (int)blockIdx.x;
    const int h = blockIdx.y;
    const int hk = h >> 2;
    const int tid = threadIdx.x;
    const size_t sbase = (size_t)h * TRI_ENT +
                         (size_t)qtile * (qtile + 1) / 2 * 4096;

    const int rg = tid >> 3;
    const int kg = tid & 7;
    const int pj = tid & 63, ph = tid >> 6;

    u64 o2[4][4];
#pragma unroll
    for (int a = 0; a < 4; a++)
#pragma unroll
        for (int b = 0; b < 4; b++) o2[a][b] = 0ull;

    for (int kt = 0; kt <= qtile; kt++) {
        __syncthreads();
        {
            const int key = tid >> 1, dh = tid & 1;
            const float* vp = Vc + (size_t)(kt * 64 + key) * (NKV * HD) + hk * HD + dh * 32;
#pragma unroll
            for (int u = 0; u < 8; u++)
                *(float4*)&Vs[key][dh * 32 + u * 4] = ((const float4*)vp)[u];
        }
        {
            const unsigned int* spw = (const unsigned int*)
                (Sc + sbase + (size_t)(kt * 64 + pj) * 64 + ph * 32);
#pragma unroll
            for (int q4 = 0; q4 < 4; q4++) {
                uint4 wv = ((const uint4*)spw)[q4];
                unsigned int ws[4] = { wv.x, wv.y, wv.z, wv.w };
#pragma unroll
                for (int wi = 0; wi < 4; wi++) {
                    unsigned int word = ws[wi];
                    int rr0 = q4 * 8 + wi * 2;
                    Ps[ph * 32 + rr0][pj]     = __uint_as_float(word << 16);
                    Ps[ph * 32 + rr0 + 1][pj] = __uint_as_float(word & 0xffff0000u);
                }
            }
        }
        __syncthreads();

#pragma unroll 2
        for (int j = 0; j < 64; j++) {
            float p0 = Ps[rg * 4 + 0][j];
            float p1 = Ps[rg * 4 + 1][j];
            float p2 = Ps[rg * 4 + 2][j];
            float p3 = Ps[rg * 4 + 3][j];
            u64 pp[4] = { pack2(p0, p0), pack2(p1, p1),
                          pack2(p2, p2), pack2(p3, p3) };
            double2 va = *(const double2*)&Vs[j][kg * 8];
            double2 vb = *(const double2*)&Vs[j][kg * 8 + 4];
            u64 vv[4] = { d2u(va.x), d2u(va.y), d2u(vb.x), d2u(vb.y) };
#pragma unroll
            for (int a = 0; a < 4; a++)
#pragma unroll
                for (int b = 0; b < 4; b++)
                    o2[a][b] = fma2(pp[a], vv[b], o2[a][b]);
        }
    }

#pragma unroll
    for (int a = 0; a < 4; a++) {
        int trow = qtile * 64 + rg * 4 + a;
        float* op = O + (size_t)trow * D_MODEL + h * HD + kg * 8;
        float f0, f1, f2, f3, f4, f5, f6, f7;
        unpack2(o2[a][0], f0, f1);
        unpack2(o2[a][1], f2, f3);
        unpack2(o2[a][2], f4, f5);
        unpack2(o2[a][3], f6, f7);
        *(float4*)&op[0] = make_float4(bf16r(f0), bf16r(f1), bf16r(f2), bf16r(f3));
        *(float4*)&op[4] = make_float4(bf16r(f4), bf16r(f5), bf16r(f6), bf16r(f7));
    }
}

// ---------------- host launcher ----------------------------------------------
extern "C" void kernel_launch(void* const* d_in, const int* in_sizes, int n_in,
                              void* d_out, int out_size) {
    (void)out_size;

    const float *x = 0, *w_o = 0, *scale_q = 0, *scale_kv = 0;
    const float *p524[2] = {0, 0}, *p262[3] = {0, 0, 0}, *p65[2] = {0, 0};
    int n524 = 0, n262 = 0, n65 = 0;
    for (int i = 0; i < n_in; i++) {
        switch (in_sizes[i]) {
            case 4194304: x = (const float*)d_in[i]; break;
            case 1048576: w_o = (const float*)d_in[i]; break;
            case 512:     scale_q  = (const float*)d_in[i]; break;
            case 256:     scale_kv = (const float*)d_in[i]; break;
            case 524288:  if (n524 < 2) p524[n524++] = (const float*)d_in[i]; break;
            case 262144:  if (n262 < 3) p262[n262++] = (const float*)d_in[i]; break;
            case 65536:   if (n65 < 2)  p65[n65++]  = (const float*)d_in[i]; break;
            default: break;
        }
    }
    const float* w_dq  = p524[0];
    const float* w_uq  = p524[1];
    const float* sin_p = p262[0];
    const float* cos_p = p262[1];
    const float* w_dkv = p262[2];
    const float* w_uk  = p65[0];
    const float* w_uv  = p65[1];
    float* out = (float*)d_out;

    float *qlat_raw, *qlat, *qb, *q_ro, *kvraw, *kvlat, *kb, *k_ro, *vb, *attn, *mg, *lg;
    __nv_bfloat16* scores;
    cudaGetSymbolAddress((void**)&qlat_raw, g_qlat_raw);
    cudaGetSymbolAddress((void**)&qlat,     g_qlat);
    cudaGetSymbolAddress((void**)&qb,       g_q);
    cudaGetSymbolAddress((void**)&q_ro,     g_q_ro);
    cudaGetSymbolAddress((void**)&kvraw,    g_kvraw);
    cudaGetSymbolAddress((void**)&kvlat,    g_kvlat);
    cudaGetSymbolAddress((void**)&kb,       g_k);
    cudaGetSymbolAddress((void**)&k_ro,     g_k_ro);
    cudaGetSymbolAddress((void**)&vb,       g_v);
    cudaGetSymbolAddress((void**)&attn,     g_attn);
    cudaGetSymbolAddress((void**)&mg,       g_m);
    cudaGetSymbolAddress((void**)&lg,       g_l);
    cudaGetSymbolAddress((void**)&scores,   g_scores);

    auto blocks = [](long long n) { return (int)((n + 255) / 256); };

    // q path
    gemm_ffma2<<<dim3(QL / 64, T_SEQ / 64), 128>>>(x, w_dq, qlat_raw,
                                                   T_SEQ, QL, D_MODEL);
    rmsnorm_kernel<<<T_SEQ, 256>>>(qlat_raw, scale_q, qlat, QL);
    gemm_ffma2<<<dim3((NH * HD) / 64, T_SEQ / 64), 128>>>(qlat, w_uq, qb,
                                                          T_SEQ, NH * HD, QL);

    // kv path
    gemm_ffma2<<<dim3(KVL / 64, T_SEQ / 64), 128>>>(x, w_dkv, kvraw,
                                                    T_SEQ, KVL, D_MODEL);
    rmsnorm_kernel<<<T_SEQ, 256>>>(kvraw, scale_kv, kvlat, KVL);
    gemm_ffma2<<<dim3((NKV * HD) / 64, T_SEQ / 64), 128>>>(kvlat, w_uk, kb,
                                                           T_SEQ, NKV * HD, KVL);
    gemm_ffma2<<<dim3((NKV * HD) / 64, T_SEQ / 64), 128>>>(kvlat, w_uv, vb,
                                                           T_SEQ, NKV * HD, KVL);

    // rope
    rope_kernel<<<blocks((long long)T_SEQ * NH * HD), 256>>>(qb, sin_p, cos_p, q_ro, NH);
    rope_kernel<<<blocks((long long)T_SEQ * NKV * HD), 256>>>(kb, sin_p, cos_p, k_ro, NKV);

    // attention: QK+softmax stats -> probs -> PV
    attn_qk_kernel<<<dim3(T_SEQ / 64, NH), 128>>>(q_ro, k_ro, mg, lg, scores);
    prob_kernel<<<dim3(NTP, NH), 256>>>(scores, mg, lg);
    attn_pv_kernel<<<dim3(T_SEQ / 64, NH), 128>>>(vb, attn, scores);

    // final projection
    gemm_ffma2<<<dim3(D_MODEL / 64, T_SEQ / 64), 128>>>(attn, w_o, out,
                                                        T_SEQ, D_MODEL, D_MODEL);
}

// round 13
// speedup vs baseline: 1.0528x; 1.0528x over previous
#include <cuda_runtime.h>
#include <cuda_bf16.h>
#include <cstdint>

#define T_SEQ   4096
#define D_MODEL 1024
#define NH      16
#define NKV     4
#define HD      64
#define QL      512
#define KVL     256
#define TRI_ENT 8519680                 // 2080 tile-pairs * 4096 entries per head

// ---------------- scratch (device globals; all f32, values bf16-rounded) -----
static __device__ float g_qlat_raw[T_SEQ * QL];
static __device__ float g_qlat    [T_SEQ * QL];
static __device__ float g_q       [T_SEQ * NH * HD];
static __device__ float g_q_ro    [T_SEQ * NH * HD];
static __device__ float g_kvraw   [T_SEQ * KVL];
static __device__ float g_kvlat   [T_SEQ * KVL];
static __device__ float g_k       [T_SEQ * NKV * HD];
static __device__ float g_k_ro    [T_SEQ * NKV * HD];
static __device__ float g_v       [T_SEQ * NKV * HD];
static __device__ float g_attn    [T_SEQ * D_MODEL];

// causal-packed raw scores: per head, per qtile, [key j][row r], bf16(q.k)
static __device__ __nv_bfloat16 g_scores[(size_t)NH * TRI_ENT];

// ---------------- helpers -----------------------------------------------------
__device__ __forceinline__ float bf16r(float x) {
    return __bfloat162float(__float2bfloat16(x));
}

typedef unsigned long long u64;

__device__ __forceinline__ u64 pack2(float lo, float hi) {
    u64 r;
    asm("mov.b64 %0, {%1, %2};" : "=l"(r) : "f"(lo), "f"(hi));
    return r;
}
__device__ __forceinline__ void unpack2(u64 v, float& lo, float& hi) {
    asm("mov.b64 {%0, %1}, %2;" : "=f"(lo), "=f"(hi) : "l"(v));
}
__device__ __forceinline__ u64 d2u(double d) {
    return (u64)__double_as_longlong(d);
}
__device__ __forceinline__ u64 fma2(u64 a, u64 b, u64 c) {
    u64 d;
    asm("fma.rn.f32x2 %0, %1, %2, %3;" : "=l"(d) : "l"(a), "l"(b), "l"(c));
    return d;
}

// Deterministic ~1-ulp exp, fmaf-only (identical since round 7).
__device__ __forceinline__ float exp_acc(float x) {
    x = fmaxf(x, -87.0f);
    float n = rintf(x * 1.44269504088896340736f);
    float r = fmaf(n, -0.693145751953125f, x);
    r = fmaf(n, -1.42860677e-06f, r);
    float p = 1.9841269841e-04f;
    p = fmaf(p, r, 1.3888888889e-03f);
    p = fmaf(p, r, 8.3333333333e-03f);
    p = fmaf(p, r, 4.1666666667e-02f);
    p = fmaf(p, r, 1.6666666667e-01f);
    p = fmaf(p, r, 0.5f);
    p = fmaf(p, r, 1.0f);
    p = fmaf(p, r, 1.0f);
    int in = (int)n;
    return p * __int_as_float((in + 127) << 23);
}

// ---------------- GEMM: 64x64 tile, BK=32, 128 threads, FFMA2 + prefetch ------
// Each output element's k-chain strictly ascending -> bit-identical to R8-R12.
__global__ void __launch_bounds__(128, 4)
gemm_ffma2(const float* __restrict__ A,
           const float* __restrict__ B,
           float* __restrict__ C,
           int M, int N, int K) {
    __shared__ float As[32][68];   // [kk][row] transposed
    __shared__ float Bs[32][68];   // [kk][col]

    const int tid = threadIdx.x;
    const int tx = tid & 15;
    const int ty = tid >> 4;
    const int row0 = blockIdx.y * 64;
    const int col0 = blockIdx.x * 64;

    const int a_row  = tid & 63;
    const int a_half = tid >> 6;
    const int b_row  = tid >> 2;
    const int b_col  = (tid & 3) * 16;

    const int nkt = K >> 5;
    float a_st[16], b_st[16];

    auto ldg_tile = [&](int kt) {
        const float* ap = A + (size_t)(row0 + a_row) * K + kt * 32 + a_half * 16;
#pragma unroll
        for (int u = 0; u < 4; u++)
            *(float4*)&a_st[u * 4] = ((const float4*)ap)[u];
        const float* bp = B + (size_t)(kt * 32 + b_row) * N + col0 + b_col;
#pragma unroll
        for (int u = 0; u < 4; u++)
            *(float4*)&b_st[u * 4] = ((const float4*)bp)[u];
    };
    auto sts_tile = [&]() {
#pragma unroll
        for (int u = 0; u < 16; u++)
            As[a_half * 16 + u][a_row] = a_st[u];
#pragma unroll
        for (int u = 0; u < 4; u++)
            *(float4*)&Bs[b_row][b_col + u * 4] = *(float4*)&b_st[u * 4];
    };

    u64 acc2[4][4];
#pragma unroll
    for (int p = 0; p < 4; p++)
#pragma unroll
        for (int j = 0; j < 4; j++) acc2[p][j] = 0ull;

    ldg_tile(0);
    sts_tile();
    __syncthreads();

    for (int kt = 0; kt < nkt; kt++) {
        if (kt + 1 < nkt) ldg_tile(kt + 1);   // overlap LDG with compute

#pragma unroll 4
        for (int kk = 0; kk < 32; kk++) {
            float4 bf = *(const float4*)&Bs[kk][tx * 4];
            u64 b0 = pack2(bf.x, bf.x);
            u64 b1 = pack2(bf.y, bf.y);
            u64 b2 = pack2(bf.z, bf.z);
            u64 b3 = pack2(bf.w, bf.w);
            double2 a01 = *(const double2*)&As[kk][ty * 8];
            double2 a23 = *(const double2*)&As[kk][ty * 8 + 4];
            u64 ap_[4] = { d2u(a01.x), d2u(a01.y), d2u(a23.x), d2u(a23.y) };
#pragma unroll
            for (int p = 0; p < 4; p++) {
                acc2[p][0] = fma2(ap_[p], b0, acc2[p][0]);
                acc2[p][1] = fma2(ap_[p], b1, acc2[p][1]);
                acc2[p][2] = fma2(ap_[p], b2, acc2[p][2]);
                acc2[p][3] = fma2(ap_[p], b3, acc2[p][3]);
            }
        }

        if (kt + 1 < nkt) {
            __syncthreads();
            sts_tile();
            __syncthreads();
        }
    }

#pragma unroll
    for (int p = 0; p < 4; p++) {
        float lo0, hi0, lo1, hi1, lo2, hi2, lo3, hi3;
        unpack2(acc2[p][0], lo0, hi0);
        unpack2(acc2[p][1], lo1, hi1);
        unpack2(acc2[p][2], lo2, hi2);
        unpack2(acc2[p][3], lo3, hi3);
        float4 ve = make_float4(bf16r(lo0), bf16r(lo1), bf16r(lo2), bf16r(lo3));
        float4 vo = make_float4(bf16r(hi0), bf16r(hi1), bf16r(hi2), bf16r(hi3));
        *(float4*)&C[(size_t)(row0 + ty * 8 + 2 * p)     * N + col0 + tx * 4] = ve;
        *(float4*)&C[(size_t)(row0 + ty * 8 + 2 * p + 1) * N + col0 + tx * 4] = vo;
    }
}

// ---------------- RMSNorm (same FP ops) ---------------------------------------
__global__ void rmsnorm_kernel(const float* __restrict__ in,
                               const float* __restrict__ scale,
                               float* __restrict__ out,
                               int cols) {
    const int row = blockIdx.x;
    const int tid = threadIdx.x;
    const float* x = in + (size_t)row * cols;
    float* y = out + (size_t)row * cols;

    __shared__ float red[256];
    float s = 0.0f;
    for (int c = tid; c < cols; c += 256) {
        float v = x[c];
        s = fmaf(v, v, s);
    }
    red[tid] = s;
    __syncthreads();
    for (int off = 128; off > 0; off >>= 1) {
        if (tid < off) red[tid] += red[tid + off];
        __syncthreads();
    }
    float rms = __fsqrt_rn(red[0] / (float)cols + 1e-6f);
    for (int c = tid; c < cols; c += 256)
        y[c] = bf16r(__fdiv_rn(x[c], rms) * scale[c]);
}

// ---------------- RoPE (same FP ops) -------------------------------------------
__global__ void rope_kernel(const float* __restrict__ in,
                            const float* __restrict__ sin_t,
                            const float* __restrict__ cos_t,
                            float* __restrict__ out,
                            int heads) {
    int idx = blockIdx.x * blockDim.x + threadIdx.x;
    int total = T_SEQ * heads * HD;
    if (idx >= total) return;
    int d = idx & 63;
    int t = (idx >> 6) / heads;
    float xv = in[idx];
    float rot = (d < 32) ? -in[idx + 32] : in[idx - 32];
    float r1 = bf16r(xv * cos_t[t * HD + d]);
    float r2 = bf16r(rot * sin_t[t * HD + d]);
    out[idx] = bf16r(r1 + r2);
}

// ---------------- causal attention: fused (R11 structure, PsT layout) ----------
// FP values/order identical to R10-R12.
__global__ void __launch_bounds__(128, 4)
attn_kernel(const float* __restrict__ Q,
            const float* __restrict__ Kc,
            const float* __restrict__ Vc,
            float* __restrict__ O,
            __nv_bfloat16* __restrict__ Sc) {
    __shared__ float QP[64][68];   // pass1: Qs[i][row]; pass3: PsT[j][row]
    __shared__ float KV[64][68];   // pass1: Ks[i][key]; pass3: Vs[j][dim]
    __shared__ float m_s[64];
    __shared__ float l_s[64];

    const int qtile = (int)gridDim.x - 1 - (int)blockIdx.x;   // heavy first
    const int h = blockIdx.y;
    const int hk = h >> 2;
    const int tid = threadIdx.x;
    const size_t sbase = (size_t)h * TRI_ENT +
                         (size_t)qtile * (qtile + 1) / 2 * 4096;

    const int rg = tid >> 3;    // 0..15 -> 4 rows each
    const int kg = tid & 7;     // 0..7  -> 8 keys/dims each

    // ---- load Q tile transposed: QP[i][row] ----
    {
        const int r_ld = tid >> 1, dh = tid & 1;
        const float* qp = Q + (size_t)(qtile * 64 + r_ld) * D_MODEL + h * HD + dh * 32;
        float qv[32];
#pragma unroll
        for (int u = 0; u < 8; u++)
            *(float4*)&qv[u * 4] = ((const float4*)qp)[u];
#pragma unroll
        for (int u = 0; u < 32; u++)
            QP[dh * 32 + u][r_ld] = qv[u];
    }

    float mreg[4] = { -1e30f, -1e30f, -1e30f, -1e30f };

    // ================= pass 1: QK GEMM, store bf16 scores, exact max =========
    for (int kt = 0; kt <= qtile; kt++) {
        __syncthreads();
        {
            const int key = tid >> 1, dh = tid & 1;
            const float* kp = Kc + (size_t)(kt * 64 + key) * (NKV * HD) + hk * HD + dh * 32;
            float kv[32];
#pragma unroll
            for (int u = 0; u < 8; u++)
                *(float4*)&kv[u * 4] = ((const float4*)kp)[u];
#pragma unroll
            for (int u = 0; u < 32; u++)
                KV[dh * 32 + u][key] = kv[u];
        }
        __syncthreads();

        u64 alo[4][4], ahi[4][4];
#pragma unroll
        for (int a = 0; a < 4; a++)
#pragma unroll
            for (int b = 0; b < 4; b++) { alo[a][b] = 0ull; ahi[a][b] = 0ull; }

#pragma unroll 8
        for (int i = 0; i < 32; i++) {
            float4 qv = *(const float4*)&QP[i][rg * 4];
            double2 ka = *(const double2*)&KV[i][kg * 8];
            double2 kb = *(const double2*)&KV[i][kg * 8 + 4];
            u64 kp_[4] = { d2u(ka.x), d2u(ka.y), d2u(kb.x), d2u(kb.y) };
            u64 q_[4] = { pack2(qv.x, qv.x), pack2(qv.y, qv.y),
                          pack2(qv.z, qv.z), pack2(qv.w, qv.w) };
#pragma unroll
            for (int a = 0; a < 4; a++)
#pragma unroll
                for (int b = 0; b < 4; b++)
                    alo[a][b] = fma2(q_[a], kp_[b], alo[a][b]);
        }
#pragma unroll 8
        for (int i = 32; i < 64; i++) {
            float4 qv = *(const float4*)&QP[i][rg * 4];
            double2 ka = *(const double2*)&KV[i][kg * 8];
            double2 kb = *(const double2*)&KV[i][kg * 8 + 4];
            u64 kp_[4] = { d2u(ka.x), d2u(ka.y), d2u(kb.x), d2u(kb.y) };
            u64 q_[4] = { pack2(qv.x, qv.x), pack2(qv.y, qv.y),
                          pack2(qv.z, qv.z), pack2(qv.w, qv.w) };
#pragma unroll
            for (int a = 0; a < 4; a++)
#pragma unroll
                for (int b = 0; b < 4; b++)
                    ahi[a][b] = fma2(q_[a], kp_[b], ahi[a][b]);
        }

        // epilogue: sum = lo + hi (same operands as R10's part+shfl), bf16, store
        float scv[8][4];   // [key][row]
#pragma unroll
        for (int b = 0; b < 4; b++)
#pragma unroll
            for (int a = 0; a < 4; a++) {
                float l0, l1, h0, h1;
                unpack2(alo[a][b], l0, l1);
                unpack2(ahi[a][b], h0, h1);
                scv[b * 2][a]     = l0 + h0;
                scv[b * 2 + 1][a] = l1 + h1;
            }
#pragma unroll
        for (int jj = 0; jj < 8; jj++) {
            int j = kg * 8 + jj;
            int gj = kt * 64 + j;
            __nv_bfloat162 pa = __floats2bfloat162_rn(scv[jj][0], scv[jj][1]);
            __nv_bfloat162 pb = __floats2bfloat162_rn(scv[jj][2], scv[jj][3]);
            uint2 st;
            st.x = *(unsigned int*)&pa;
            st.y = *(unsigned int*)&pb;
            *(uint2*)(Sc + sbase + (size_t)gj * 64 + rg * 4) = st;
#pragma unroll
            for (int a = 0; a < 4; a++) {
                float s = bf16r(scv[jj][a]) * 0.125f;
                int trow = qtile * 64 + rg * 4 + a;
                if (gj <= trow) mreg[a] = fmaxf(mreg[a], s);
            }
        }
    }

    // reduce max across the 8 kg lanes (fmaxf exact in any order)
#pragma unroll
    for (int a = 0; a < 4; a++) {
        float v = mreg[a];
        v = fmaxf(v, __shfl_xor_sync(0xffffffffu, v, 1));
        v = fmaxf(v, __shfl_xor_sync(0xffffffffu, v, 2));
        v = fmaxf(v, __shfl_xor_sync(0xffffffffu, v, 4));
        mreg[a] = v;
    }
    if (kg == 0) {
#pragma unroll
        for (int a = 0; a < 4; a++) m_s[rg * 4 + a] = mreg[a];
    }
    __syncthreads();

    // ================= pass 2: l chain (byte-identical structure to R10) =====
    {
        const int r2 = tid >> 1, hf2 = tid & 1;
        const unsigned pair_mask = 0x3u << ((tid & 31) & ~1);
        const float m = m_s[r2];
        float l = 0.0f;
        for (int kt = 0; kt <= qtile; kt++) {
            const int jmax = (kt == qtile) ? r2 : 63;
            int j = 0;
            for (; j + 1 <= jmax; j += 2) {
                int jm = j + hf2;
                float s = __bfloat162float(Sc[sbase + (size_t)(kt * 64 + jm) * 64 + r2]) * 0.125f;
                float e = exp_acc(s - m);
                float eo = __shfl_xor_sync(pair_mask, e, 1);
                float e_even = hf2 ? eo : e;
                float e_odd  = hf2 ? e  : eo;
                l += e_even;
                l += e_odd;
            }
            if (j <= jmax) {
                float s = __bfloat162float(Sc[sbase + (size_t)(kt * 64 + j) * 64 + r2]) * 0.125f;
                l += exp_acc(s - m);
            }
        }
        if (hf2 == 0) l_s[r2] = l;
    }
    __syncthreads();

    // ================= pass 3: probs (PsT[j][row]) + PV GEMM =================
    u64 o2[4][4];
#pragma unroll
    for (int a = 0; a < 4; a++)
#pragma unroll
        for (int b = 0; b < 4; b++) o2[a][b] = 0ull;

    const int pj = tid & 63, ph = tid >> 6;

    for (int kt = 0; kt <= qtile; kt++) {
        __syncthreads();   // protect prior tile's PsT/Vs reads
        // load V tile straight: Vs[j][dim]
        {
            const int key = tid >> 1, dh = tid & 1;
            const float* vp = Vc + (size_t)(kt * 64 + key) * (NKV * HD) + hk * HD + dh * 32;
#pragma unroll
            for (int u = 0; u < 8; u++)
                *(float4*)&KV[key][dh * 32 + u * 4] = ((const float4*)vp)[u];
        }
        // probs: thread owns key pj, rows ph*32..+31 -> PsT[pj][row] (float4 STS)
        {
            const unsigned int* spw = (const unsigned int*)
                (Sc + sbase + (size_t)(kt * 64 + pj) * 64 + ph * 32);
            const int gj = kt * 64 + pj;
#pragma unroll
            for (int q4 = 0; q4 < 4; q4++) {
                uint4 wv = ((const uint4*)spw)[q4];
                unsigned int ws[4] = { wv.x, wv.y, wv.z, wv.w };
                float pv[8];
#pragma unroll
                for (int wi = 0; wi < 4; wi++) {
                    unsigned int word = ws[wi];
                    int rr0 = wi * 2;
#pragma unroll
                    for (int e = 0; e < 2; e++) {
                        int row = ph * 32 + q4 * 8 + rr0 + e;
                        float p = 0.0f;
                        if (gj <= qtile * 64 + row) {
                            float sv = __uint_as_float(e ? (word & 0xffff0000u)
                                                         : (word << 16));
                            float s = sv * 0.125f;
                            p = bf16r(__fdiv_rn(exp_acc(s - m_s[row]), l_s[row]));
                        }
                        pv[rr0 + e] = p;
                    }
                }
                *(float4*)&QP[pj][ph * 32 + q4 * 8]     = *(float4*)&pv[0];
                *(float4*)&QP[pj][ph * 32 + q4 * 8 + 4] = *(float4*)&pv[4];
            }
        }
        __syncthreads();

        // PV: rows rg*4..+3, dims kg*8..+7, j ascending (zero-p adds exact)
#pragma unroll 2
        for (int j = 0; j < 64; j++) {
            float4 pf = *(const float4*)&QP[j][rg * 4];
            u64 pp[4] = { pack2(pf.x, pf.x), pack2(pf.y, pf.y),
                          pack2(pf.z, pf.z), pack2(pf.w, pf.w) };
            double2 va = *(const double2*)&KV[j][kg * 8];
            double2 vb = *(const double2*)&KV[j][kg * 8 + 4];
            u64 vv[4] = { d2u(va.x), d2u(va.y), d2u(vb.x), d2u(vb.y) };
#pragma unroll
            for (int a = 0; a < 4; a++)
#pragma unroll
                for (int b = 0; b < 4; b++)
                    o2[a][b] = fma2(pp[a], vv[b], o2[a][b]);
        }
    }

    // epilogue: bf16-rounded outputs
#pragma unroll
    for (int a = 0; a < 4; a++) {
        int trow = qtile * 64 + rg * 4 + a;
        float* op = O + (size_t)trow * D_MODEL + h * HD + kg * 8;
        float f0, f1, f2, f3, f4, f5, f6, f7;
        unpack2(o2[a][0], f0, f1);
        unpack2(o2[a][1], f2, f3);
        unpack2(o2[a][2], f4, f5);
        unpack2(o2[a][3], f6, f7);
        *(float4*)&op[0] = make_float4(bf16r(f0), bf16r(f1), bf16r(f2), bf16r(f3));
        *(float4*)&op[4] = make_float4(bf16r(f4), bf16r(f5), bf16r(f6), bf16r(f7));
    }
}

// ---------------- host launcher ----------------------------------------------
extern "C" void kernel_launch(void* const* d_in, const int* in_sizes, int n_in,
                              void* d_out, int out_size) {
    (void)out_size;

    const float *x = 0, *w_o = 0, *scale_q = 0, *scale_kv = 0;
    const float *p524[2] = {0, 0}, *p262[3] = {0, 0, 0}, *p65[2] = {0, 0};
    int n524 = 0, n262 = 0, n65 = 0;
    for (int i = 0; i < n_in; i++) {
        switch (in_sizes[i]) {
            case 4194304: x = (const float*)d_in[i]; break;
            case 1048576: w_o = (const float*)d_in[i]; break;
            case 512:     scale_q  = (const float*)d_in[i]; break;
            case 256:     scale_kv = (const float*)d_in[i]; break;
            case 524288:  if (n524 < 2) p524[n524++] = (const float*)d_in[i]; break;
            case 262144:  if (n262 < 3) p262[n262++] = (const float*)d_in[i]; break;
            case 65536:   if (n65 < 2)  p65[n65++]  = (const float*)d_in[i]; break;
            default: break;
        }
    }
    const float* w_dq  = p524[0];
    const float* w_uq  = p524[1];
    const float* sin_p = p262[0];
    const float* cos_p = p262[1];
    const float* w_dkv = p262[2];
    const float* w_uk  = p65[0];
    const float* w_uv  = p65[1];
    float* out = (float*)d_out;

    float *qlat_raw, *qlat, *qb, *q_ro, *kvraw, *kvlat, *kb, *k_ro, *vb, *attn;
    __nv_bfloat16* scores;
    cudaGetSymbolAddress((void**)&qlat_raw, g_qlat_raw);
    cudaGetSymbolAddress((void**)&qlat,     g_qlat);
    cudaGetSymbolAddress((void**)&qb,       g_q);
    cudaGetSymbolAddress((void**)&q_ro,     g_q_ro);
    cudaGetSymbolAddress((void**)&kvraw,    g_kvraw);
    cudaGetSymbolAddress((void**)&kvlat,    g_kvlat);
    cudaGetSymbolAddress((void**)&kb,       g_k);
    cudaGetSymbolAddress((void**)&k_ro,     g_k_ro);
    cudaGetSymbolAddress((void**)&vb,       g_v);
    cudaGetSymbolAddress((void**)&attn,     g_attn);
    cudaGetSymbolAddress((void**)&scores,   g_scores);

    auto blocks = [](long long n) { return (int)((n + 255) / 256); };

    // q path
    gemm_ffma2<<<dim3(QL / 64, T_SEQ / 64), 128>>>(x, w_dq, qlat_raw,
                                                   T_SEQ, QL, D_MODEL);
    rmsnorm_kernel<<<T_SEQ, 256>>>(qlat_raw, scale_q, qlat, QL);
    gemm_ffma2<<<dim3((NH * HD) / 64, T_SEQ / 64), 128>>>(qlat, w_uq, qb,
                                                          T_SEQ, NH * HD, QL);

    // kv path
    gemm_ffma2<<<dim3(KVL / 64, T_SEQ / 64), 128>>>(x, w_dkv, kvraw,
                                                    T_SEQ, KVL, D_MODEL);
    rmsnorm_kernel<<<T_SEQ, 256>>>(kvraw, scale_kv, kvlat, KVL);
    gemm_ffma2<<<dim3((NKV * HD) / 64, T_SEQ / 64), 128>>>(kvlat, w_uk, kb,
                                                           T_SEQ, NKV * HD, KVL);
    gemm_ffma2<<<dim3((NKV * HD) / 64, T_SEQ / 64), 128>>>(kvlat, w_uv, vb,
                                                           T_SEQ, NKV * HD, KVL);

    // rope
    rope_kernel<<<blocks((long long)T_SEQ * NH * HD), 256>>>(qb, sin_p, cos_p, q_ro, NH);
    rope_kernel<<<blocks((long long)T_SEQ * NKV * HD), 256>>>(kb, sin_p, cos_p, k_ro, NKV);

    // attention (fused)
    attn_kernel<<<dim3(T_SEQ / 64, NH), 128>>>(q_ro, k_ro, vb, attn, scores);

    // final projection
    gemm_ffma2<<<dim3(D_MODEL / 64, T_SEQ / 64), 128>>>(attn, w_o, out,
                                                        T_SEQ, D_MODEL, D_MODEL);
}